// round 3
// baseline (speedup 1.0000x reference)
#include <cuda_runtime.h>
#include <math.h>

// ---------------- problem constants ----------------
#define BB 4
#define CC 512
#define CI 256
#define TT 16
#define HH 28
#define WW 28
#define NN 12544            // TT*HH*WW
#define TP 8
#define HP 14
#define WP 14
#define MM 1568             // TP*HP*WP
#define EPS 1e-5f

// ---------------- scratch layout (floats) ----------------
// theta : (b, n, ci)        12,845,056
// g     : (b, m, ci)         1,605,632
// phi   : (b, m, ci)         1,605,632
// f     : (b, n, m)         78,675,968   (also aliases gfull/phifull before f is computed)
// y     : (b, n, ci)        12,845,056
// wy    : (b, c, n)         25,690,112
#define OFF_THETA 0LL
#define OFF_G     12845056LL
#define OFF_PHI   14450688LL
#define OFF_F     16056320LL
#define OFF_Y     94732288LL
#define OFF_WY    107577344LL
#define SCRATCH_TOTAL 133267456LL

__device__ __align__(16) float d_scratch[SCRATCH_TOTAL];
__device__ __align__(16) float d_stats[2 * CC];

// ---------------- generic tiled SGEMM ----------------
// C(Mrows x Ncols) = A(Mrows x K, row-major, lda) * B + bias[row]
// BL == 0 : B is (K x Ncols) row-major, ldb      (NN)
// BL == 1 : B is (Ncols x K) row-major, ldb      (NT, i.e. B^T)
// EPI == 0: C[row*ldc + col]       (row-major)
// EPI == 1: C[col*ldc + row]       (transposed write)
// Mrows must be a multiple of 128; K a multiple of 8; Ncols arbitrary.
template <int BL, int EPI>
__global__ __launch_bounds__(256)
void sgemm_kernel(const float* __restrict__ A, const float* __restrict__ Bm,
                  float* __restrict__ Cm, const float* __restrict__ bias,
                  int Ncols, int K, int lda, int ldb, int ldc,
                  long long sA, long long sB, long long sC)
{
    __shared__ float As[8][128];
    __shared__ float Bs[8][128];

    const int bz = blockIdx.z;
    A  += (long long)bz * sA;
    Bm += (long long)bz * sB;
    Cm += (long long)bz * sC;

    const int n0 = blockIdx.x * 128;
    const int m0 = blockIdx.y * 128;
    const int tid = threadIdx.x;
    const int tx = tid & 15;
    const int ty = tid >> 4;

    float acc[8][8];
#pragma unroll
    for (int i = 0; i < 8; i++)
#pragma unroll
        for (int j = 0; j < 8; j++) acc[i][j] = 0.f;

    const int arow = tid >> 1;
    const int ak4  = (tid & 1) * 4;

    for (int k0 = 0; k0 < K; k0 += 8) {
        // ---- load A tile (always K-contiguous rows) ----
        float4 av = *(const float4*)(A + (long long)(m0 + arow) * lda + k0 + ak4);
        As[ak4 + 0][arow] = av.x;
        As[ak4 + 1][arow] = av.y;
        As[ak4 + 2][arow] = av.z;
        As[ak4 + 3][arow] = av.w;

        // ---- load B tile ----
        if (BL == 0) {
            const int bk = tid >> 5;
            const int bn = (tid & 31) * 4;
            const int gn = n0 + bn;
            float4 bv;
            const float* bp = Bm + (long long)(k0 + bk) * ldb + gn;
            if (gn + 3 < Ncols) {
                bv = *(const float4*)bp;
            } else {
                bv.x = (gn + 0 < Ncols) ? bp[0] : 0.f;
                bv.y = (gn + 1 < Ncols) ? bp[1] : 0.f;
                bv.z = (gn + 2 < Ncols) ? bp[2] : 0.f;
                bv.w = (gn + 3 < Ncols) ? bp[3] : 0.f;
            }
            *(float4*)&Bs[bk][bn] = bv;
        } else {
            const int bn  = tid >> 1;
            const int bk4 = (tid & 1) * 4;
            const int gn  = n0 + bn;
            float4 bv = make_float4(0.f, 0.f, 0.f, 0.f);
            if (gn < Ncols)
                bv = *(const float4*)(Bm + (long long)gn * ldb + k0 + bk4);
            Bs[bk4 + 0][bn] = bv.x;
            Bs[bk4 + 1][bn] = bv.y;
            Bs[bk4 + 2][bn] = bv.z;
            Bs[bk4 + 3][bn] = bv.w;
        }
        __syncthreads();

#pragma unroll
        for (int kk = 0; kk < 8; kk++) {
            float a[8], b[8];
            *(float4*)&a[0] = *(const float4*)&As[kk][ty * 4];
            *(float4*)&a[4] = *(const float4*)&As[kk][64 + ty * 4];
            *(float4*)&b[0] = *(const float4*)&Bs[kk][tx * 4];
            *(float4*)&b[4] = *(const float4*)&Bs[kk][64 + tx * 4];
#pragma unroll
            for (int i = 0; i < 8; i++)
#pragma unroll
                for (int j = 0; j < 8; j++)
                    acc[i][j] += a[i] * b[j];
        }
        __syncthreads();
    }

    // ---- epilogue ----
#pragma unroll
    for (int i = 0; i < 8; i++) {
        const int row = m0 + ((i < 4) ? (ty * 4 + i) : (64 + ty * 4 + i - 4));
        const float bi = bias ? bias[row] : 0.f;
#pragma unroll
        for (int j = 0; j < 8; j++) {
            const int col = n0 + ((j < 4) ? (tx * 4 + j) : (64 + tx * 4 + j - 4));
            if (col < Ncols) {
                const float v = acc[i][j] + bi;
                if (EPI == 0) Cm[(long long)row * ldc + col] = v;
                else          Cm[(long long)col * ldc + row] = v;
            }
        }
    }
}

// ---------------- 2x2x2 max pool + transpose to (b, m, ci) ----------------
__global__ void pool_kernel(const float* __restrict__ gfull,
                            const float* __restrict__ pfull,
                            float* __restrict__ gout,
                            float* __restrict__ pout)
{
    const int bc = blockIdx.x;            // b*CI + ci
    const int b  = bc / CI;
    const int ci = bc % CI;
    const int tp = blockIdx.y;
    const int tid = threadIdx.x;
    if (tid >= HP * WP) return;
    const int hp = tid / WP;
    const int wp = tid % WP;

    const float* gb = gfull + (long long)bc * NN;
    const float* pb = pfull + (long long)bc * NN;
    float gm = -1e30f, pm = -1e30f;
#pragma unroll
    for (int dt = 0; dt < 2; dt++)
#pragma unroll
        for (int dh = 0; dh < 2; dh++)
#pragma unroll
            for (int dw = 0; dw < 2; dw++) {
                const int n = (2 * tp + dt) * (HH * WW) + (2 * hp + dh) * WW + (2 * wp + dw);
                gm = fmaxf(gm, gb[n]);
                pm = fmaxf(pm, pb[n]);
            }
    const int m = (tp * HP + hp) * WP + wp;
    gout[((long long)b * MM + m) * CI + ci] = gm;
    pout[((long long)b * MM + m) * CI + ci] = pm;
}

// ---------------- row softmax over M=1568, in place ----------------
__global__ void softmax_kernel(float* __restrict__ f)
{
    const long long row = blockIdx.x;
    float* p = f + row * MM;
    const int tid = threadIdx.x;
    __shared__ float red[128];

    float mx = -1e30f;
    for (int i = tid; i < MM; i += 128) mx = fmaxf(mx, p[i]);
    red[tid] = mx;
    __syncthreads();
    for (int s = 64; s > 0; s >>= 1) {
        if (tid < s) red[tid] = fmaxf(red[tid], red[tid + s]);
        __syncthreads();
    }
    mx = red[0];
    __syncthreads();

    float sum = 0.f;
    for (int i = tid; i < MM; i += 128) {
        const float e = __expf(p[i] - mx);
        p[i] = e;
        sum += e;
    }
    red[tid] = sum;
    __syncthreads();
    for (int s = 64; s > 0; s >>= 1) {
        if (tid < s) red[tid] += red[tid + s];
        __syncthreads();
    }
    const float inv = 1.f / red[0];
    for (int i = tid; i < MM; i += 128) p[i] *= inv;
}

// ---------------- per-channel batch stats over (b, n) ----------------
__global__ void stats_kernel(const float* __restrict__ wy, float* __restrict__ stats)
{
    const int c = blockIdx.x;
    const int tid = threadIdx.x;
    float s = 0.f, ss = 0.f;
    for (int b = 0; b < BB; b++) {
        const float* p = wy + ((long long)b * CC + c) * NN;
        for (int i = tid; i < NN; i += 256) {
            const float v = p[i];
            s += v;
            ss += v * v;
        }
    }
    __shared__ float rs[256], rss[256];
    rs[tid] = s;
    rss[tid] = ss;
    __syncthreads();
    for (int st = 128; st > 0; st >>= 1) {
        if (tid < st) { rs[tid] += rs[tid + st]; rss[tid] += rss[tid + st]; }
        __syncthreads();
    }
    if (tid == 0) {
        const float cnt = (float)(BB * NN);
        const float mean = rs[0] / cnt;
        const float var = rss[0] / cnt - mean * mean;
        stats[c] = mean;
        stats[CC + c] = rsqrtf(var + EPS);
    }
}

// ---------------- BN affine + residual ----------------
__global__ void final_kernel(const float* __restrict__ wy, const float* __restrict__ x,
                             const float* __restrict__ gamma, const float* __restrict__ beta,
                             const float* __restrict__ stats, float* __restrict__ out)
{
    const long long idx = (long long)blockIdx.x * blockDim.x + threadIdx.x;
    const long long total = (long long)BB * CC * NN / 4;
    if (idx >= total) return;
    const int c = (int)((idx * 4 / NN) % CC);
    const float mean = stats[c];
    const float rstd = stats[CC + c];
    const float g = gamma[c] * rstd;
    const float bt = beta[c] - mean * g;
    const float4 wv = ((const float4*)wy)[idx];
    const float4 xv = ((const float4*)x)[idx];
    float4 o;
    o.x = wv.x * g + bt + xv.x;
    o.y = wv.y * g + bt + xv.y;
    o.z = wv.z * g + bt + xv.z;
    o.w = wv.w * g + bt + xv.w;
    ((float4*)out)[idx] = o;
}

// ---------------- launch ----------------
extern "C" void kernel_launch(void* const* d_in, const int* in_sizes, int n_in,
                              void* d_out, int out_size)
{
    const float* x       = (const float*)d_in[0];
    const float* g_w     = (const float*)d_in[1];
    const float* g_b     = (const float*)d_in[2];
    const float* theta_w = (const float*)d_in[3];
    const float* theta_b = (const float*)d_in[4];
    const float* phi_w   = (const float*)d_in[5];
    const float* phi_b   = (const float*)d_in[6];
    const float* W_w     = (const float*)d_in[7];
    const float* W_b     = (const float*)d_in[8];
    const float* gamma   = (const float*)d_in[9];
    const float* beta    = (const float*)d_in[10];
    float* out = (float*)d_out;

    float* S = nullptr;
    float* stats = nullptr;
    cudaGetSymbolAddress((void**)&S, d_scratch);
    cudaGetSymbolAddress((void**)&stats, d_stats);

    float* theta   = S + OFF_THETA;
    float* gp      = S + OFF_G;
    float* php     = S + OFF_PHI;
    float* f       = S + OFF_F;
    float* y       = S + OFF_Y;
    float* wy      = S + OFF_WY;
    float* gfull   = S + OFF_F;               // alias: consumed before f is written
    float* phifull = S + OFF_F + OFF_G;       // alias (OFF_G == size of theta block? no —) 

    // NOTE: phifull must not overlap gfull; gfull is B*CI*NN = 12,845,056 floats.
    phifull = S + OFF_F + 12845056LL;

    const long long xStride = (long long)CC * NN;

    // 1) theta conv: (CI x N) = theta_w(CI x C) @ X(C x N), write transposed -> theta(b,n,ci)
    sgemm_kernel<0, 1><<<dim3(NN / 128, CI / 128, BB), 256>>>(
        theta_w, x, theta, theta_b, NN, CC, CC, NN, CI,
        0LL, xStride, (long long)NN * CI);

    // 2) g conv (full res) -> gfull(b,ci,n)
    sgemm_kernel<0, 0><<<dim3(NN / 128, CI / 128, BB), 256>>>(
        g_w, x, gfull, g_b, NN, CC, CC, NN, NN,
        0LL, xStride, (long long)CI * NN);

    // 3) phi conv (full res) -> phifull(b,ci,n)
    sgemm_kernel<0, 0><<<dim3(NN / 128, CI / 128, BB), 256>>>(
        phi_w, x, phifull, phi_b, NN, CC, CC, NN, NN,
        0LL, xStride, (long long)CI * NN);

    // 4) 2x2x2 maxpool + transpose -> g(b,m,ci), phi(b,m,ci)
    pool_kernel<<<dim3(BB * CI, TP), 196>>>(gfull, phifull, gp, php);

    // 5) f = theta @ phi^T : (N x M), K=CI   (overwrites the gfull/phifull alias region)
    sgemm_kernel<1, 0><<<dim3((MM + 127) / 128, NN / 128, BB), 256>>>(
        theta, php, f, nullptr, MM, CI, CI, CI, MM,
        (long long)NN * CI, (long long)MM * CI, (long long)NN * MM);

    // 6) softmax over last dim, in place
    softmax_kernel<<<BB * NN, 128>>>(f);

    // 7) y = f @ g : (N x CI), K=M
    sgemm_kernel<0, 0><<<dim3(CI / 128, NN / 128, BB), 256>>>(
        f, gp, y, nullptr, CI, MM, MM, CI, CI,
        (long long)NN * MM, (long long)MM * CI, (long long)NN * CI);

    // 8) wy = W_w @ y^T : (C x N), K=CI
    sgemm_kernel<1, 0><<<dim3(NN / 128, CC / 128, BB), 256>>>(
        W_w, y, wy, W_b, NN, CI, CI, CI, NN,
        0LL, (long long)NN * CI, (long long)CC * NN);

    // 9) BN batch stats per channel
    stats_kernel<<<CC, 256>>>(wy, stats);

    // 10) BN affine + residual
    const long long total4 = (long long)BB * CC * NN / 4;
    final_kernel<<<(unsigned)((total4 + 255) / 256), 256>>>(wy, x, gamma, beta, stats, out);
}

// round 5
// speedup vs baseline: 1.2163x; 1.2163x over previous
#include <cuda_runtime.h>
#include <cuda_bf16.h>
#include <stdint.h>
#include <math.h>

typedef __nv_bfloat16 bf16;
typedef unsigned int u32;

// ---------------- problem constants ----------------
#define BB 4
#define CCH 512
#define CIn 256
#define NN 12544
#define MMr 1568          // real pooled positions
#define MP_Y 1600         // pad for y-GEMM K (25*64)
#define MP_F 1664         // pad for f-GEMM N (13*128)
#define EPS 1e-5f

// ---------------- scratch layout (byte offsets) ----------------
#define XT_HI   0ULL
#define XT_LO   51380224ULL
#define GFULL   102760448ULL
#define PHIFULL 154140672ULL
#define F_OFF   0ULL            // 334,987,264 B, aliases XT/GFULL/PHIFULL (dead by then)
#define TH_HI   334987264ULL
#define TH_LO   360677376ULL
#define GT_HI   386367488ULL
#define GT_LO   389644288ULL
#define PHP_HI  392921088ULL
#define PHP_LO  396328960ULL
#define P_HI    399736832ULL
#define P_LO    560300032ULL
#define Y_HI    334987264ULL    // alias TH_HI (theta dead after f GEMM)
#define Y_LO    360677376ULL
#define WY_OFF  399736832ULL    // alias P_HI (p dead after y GEMM)
#define W8_OFF  720863232ULL
#define PART_OFF 722960384ULL
#define SCRATCH_BYTES 723400704ULL

__device__ __align__(128) unsigned char d_scratch[SCRATCH_BYTES];
__device__ __align__(16) float d_stats[2 * CCH];

// ---------------- helpers ----------------
__device__ __forceinline__ u32 smem_u32(const void* p) {
    u32 a;
    asm("{ .reg .u64 t; cvta.to.shared.u64 t, %1; cvt.u32.u64 %0, t; }" : "=r"(a) : "l"(p));
    return a;
}
__device__ __forceinline__ void ldsm4(u32& r0, u32& r1, u32& r2, u32& r3, u32 addr) {
    asm volatile("ldmatrix.sync.aligned.m8n8.x4.shared.b16 {%0,%1,%2,%3}, [%4];"
                 : "=r"(r0), "=r"(r1), "=r"(r2), "=r"(r3) : "r"(addr));
}
__device__ __forceinline__ void mma16816(float* d, const u32* a, const u32* b) {
    asm volatile(
        "mma.sync.aligned.m16n8k16.row.col.f32.bf16.bf16.f32 "
        "{%0,%1,%2,%3},{%4,%5,%6,%7},{%8,%9},{%0,%1,%2,%3};"
        : "+f"(d[0]), "+f"(d[1]), "+f"(d[2]), "+f"(d[3])
        : "r"(a[0]), "r"(a[1]), "r"(a[2]), "r"(a[3]), "r"(b[0]), "r"(b[1]));
}
__device__ __forceinline__ u32 sw128(u32 off) { return off ^ ((off >> 3) & 0x70); }

// ---------------- mma.sync split-bf16 GEMM ----------------
// D = A_hi*B_hi^T + A_lo*B_hi^T + A_hi*B_lo^T  (3 K-passes, fp32 accum)
// A planes: (Mtot x K) bf16 row-major. B planes: (Ntot x K) bf16 row-major.
// CTA tile 128x128, BK=64, 8 warps (2M x 4N), warp tile 64x32.
// EPI 0: fp32 C row-major (ldc) + optional col bias.
// EPI 1: bf16 hi/lo plane outputs + optional col bias.
template <int EPI>
__global__ __launch_bounds__(256)
void tgemm(const bf16* __restrict__ Ahi, const bf16* __restrict__ Alo,
           const bf16* __restrict__ Bhi, const bf16* __restrict__ Blo,
           float* __restrict__ Cf, bf16* __restrict__ Chi, bf16* __restrict__ Clo,
           const float* __restrict__ bias,
           int K, int ldc, long long sA, long long sB, long long sC)
{
    extern __shared__ __align__(1024) unsigned char sm[];
    const int tid = threadIdx.x;
    const int wid = tid >> 5;
    const int lane = tid & 31;
    const int m0 = blockIdx.x * 128;
    const int n0 = blockIdx.y * 128;
    const long long bz = blockIdx.z;
    Ahi += bz * sA; Alo += bz * sA;
    Bhi += bz * sB; Blo += bz * sB;

    const int Kc = K >> 6;
    const int total = 3 * Kc;

    // ---- global load mapping: thread -> (row, 64B segment) ----
    const int arow = tid & 127;
    const int ac = (tid >> 7) * 32;                 // element offset (32 bf16 = 64B)
    const long long ga = (long long)(m0 + arow) * K + ac;
    const long long gb = (long long)(n0 + arow) * K + ac;
    u32 soff[4];
#pragma unroll
    for (int i = 0; i < 4; i++)
        soff[i] = sw128((u32)arow * 128 + (u32)ac * 2 + i * 16);

    // ---- per-lane ldmatrix bases ----
    const int wm = wid >> 2;
    const int wn = wid & 3;
    const int rowA = wm * 64 + ((lane >> 3) & 1) * 8 + (lane & 7);
    const u32 kbA = (u32)(lane >> 4) * 16;
    const int rowB = wn * 32 + ((lane >> 4) & 1) * 8 + (lane & 7);
    const u32 kbB = (u32)((lane >> 3) & 1) * 16;
    const u32 sbase = smem_u32(sm);

    float acc[4][4][4];
#pragma unroll
    for (int mt = 0; mt < 4; mt++)
#pragma unroll
        for (int nt = 0; nt < 4; nt++)
#pragma unroll
            for (int q = 0; q < 4; q++) acc[mt][nt][q] = 0.f;

    float4 ca[4], cb[4];
#pragma unroll
    for (int i = 0; i < 4; i++) {
        ca[i] = *(const float4*)(Ahi + ga + i * 8);
        cb[i] = *(const float4*)(Bhi + gb + i * 8);
    }

    for (int it = 0; it < total; it++) {
        // prefetch next chunk into regs
        float4 na[4], nb[4];
        if (it + 1 < total) {
            const int nit = it + 1;
            const int p = nit / Kc;
            const int k0 = (nit - p * Kc) << 6;
            const bf16* A = (p == 1) ? Alo : Ahi;
            const bf16* B = (p == 2) ? Blo : Bhi;
#pragma unroll
            for (int i = 0; i < 4; i++) {
                na[i] = *(const float4*)(A + ga + k0 + i * 8);
                nb[i] = *(const float4*)(B + gb + k0 + i * 8);
            }
        }
        // store current chunk to smem stage
        unsigned char* As_ = sm + (it & 1) * 32768;
#pragma unroll
        for (int i = 0; i < 4; i++) {
            *(float4*)(As_ + soff[i]) = ca[i];
            *(float4*)(As_ + 16384 + soff[i]) = cb[i];
        }
        __syncthreads();

        const u32 sA32 = sbase + (it & 1) * 32768;
        const u32 sB32 = sA32 + 16384;
#pragma unroll
        for (int kk = 0; kk < 4; kk++) {
            u32 af[4][4];
#pragma unroll
            for (int mt = 0; mt < 4; mt++) {
                u32 off = (u32)(rowA + mt * 16) * 128 + (u32)kk * 32 + kbA;
                ldsm4(af[mt][0], af[mt][1], af[mt][2], af[mt][3], sA32 + sw128(off));
            }
            u32 bfr[2][4];
#pragma unroll
            for (int nt2 = 0; nt2 < 2; nt2++) {
                u32 off = (u32)(rowB + nt2 * 16) * 128 + (u32)kk * 32 + kbB;
                ldsm4(bfr[nt2][0], bfr[nt2][1], bfr[nt2][2], bfr[nt2][3], sB32 + sw128(off));
            }
#pragma unroll
            for (int mt = 0; mt < 4; mt++)
#pragma unroll
                for (int nt = 0; nt < 4; nt++)
                    mma16816(acc[mt][nt], af[mt], &bfr[nt >> 1][(nt & 1) * 2]);
        }
        __syncthreads();
#pragma unroll
        for (int i = 0; i < 4; i++) { ca[i] = na[i]; cb[i] = nb[i]; }
    }

    // ---- epilogue ----
    const int r0 = m0 + wm * 64 + (lane >> 2);
    const int cb0 = n0 + wn * 32 + (lane & 3) * 2;
#pragma unroll
    for (int nt = 0; nt < 4; nt++) {
        const int c = cb0 + nt * 8;
        const float b0v = bias ? bias[c] : 0.f;
        const float b1v = bias ? bias[c + 1] : 0.f;
#pragma unroll
        for (int mt = 0; mt < 4; mt++) {
            const long long ra = r0 + mt * 16;
            const long long rb = ra + 8;
            float v0 = acc[mt][nt][0] + b0v;
            float v1 = acc[mt][nt][1] + b1v;
            float v2 = acc[mt][nt][2] + b0v;
            float v3 = acc[mt][nt][3] + b1v;
            if (EPI == 0) {
                float* base = Cf + bz * sC;
                *(float2*)(base + ra * ldc + c) = make_float2(v0, v1);
                *(float2*)(base + rb * ldc + c) = make_float2(v2, v3);
            } else {
                bf16 h0 = __float2bfloat16(v0), h1 = __float2bfloat16(v1);
                bf16 h2 = __float2bfloat16(v2), h3 = __float2bfloat16(v3);
                bf16 l0 = __float2bfloat16(v0 - __bfloat162float(h0));
                bf16 l1 = __float2bfloat16(v1 - __bfloat162float(h1));
                bf16 l2 = __float2bfloat16(v2 - __bfloat162float(h2));
                bf16 l3 = __float2bfloat16(v3 - __bfloat162float(h3));
                bf16* hb = Chi + bz * sC;
                bf16* lb = Clo + bz * sC;
                *(u32*)(hb + ra * ldc + c) = (u32)__bfloat16_as_ushort(h0) | ((u32)__bfloat16_as_ushort(h1) << 16);
                *(u32*)(hb + rb * ldc + c) = (u32)__bfloat16_as_ushort(h2) | ((u32)__bfloat16_as_ushort(h3) << 16);
                *(u32*)(lb + ra * ldc + c) = (u32)__bfloat16_as_ushort(l0) | ((u32)__bfloat16_as_ushort(l1) << 16);
                *(u32*)(lb + rb * ldc + c) = (u32)__bfloat16_as_ushort(l2) | ((u32)__bfloat16_as_ushort(l3) << 16);
            }
        }
    }
}

// ---------------- fp32 -> bf16 hi/lo split ----------------
__global__ void split_kernel(const float* __restrict__ src, bf16* __restrict__ hi,
                             bf16* __restrict__ lo, int n)
{
    int i = blockIdx.x * 256 + threadIdx.x;
    if (i < n) {
        float v = src[i];
        bf16 h = __float2bfloat16(v);
        hi[i] = h;
        lo[i] = __float2bfloat16(v - __bfloat162float(h));
    }
}

// ---------------- zero fill ----------------
__global__ void zero_kernel(float4* __restrict__ p, long long n4)
{
    long long i = (long long)blockIdx.x * 256 + threadIdx.x;
    const long long stride = (long long)gridDim.x * 256;
    for (; i < n4; i += stride) p[i] = make_float4(0.f, 0.f, 0.f, 0.f);
}

// ---------------- transpose x (b,512,N) -> xT hi/lo (b,N,512) ----------------
__global__ void xpose_kernel(const float* __restrict__ x, bf16* __restrict__ xhi,
                             bf16* __restrict__ xlo)
{
    __shared__ float t[32][33];
    const int b = blockIdx.z;
    const int n0 = blockIdx.x * 32;
    const int c0 = blockIdx.y * 32;
    const int tx = threadIdx.x, ty = threadIdx.y;
    const float* xb = x + (long long)b * CCH * NN;
#pragma unroll
    for (int k = 0; k < 4; k++)
        t[ty + k * 8][tx] = xb[(long long)(c0 + ty + k * 8) * NN + n0 + tx];
    __syncthreads();
    bf16* hb = xhi + (long long)b * NN * CCH;
    bf16* lb = xlo + (long long)b * NN * CCH;
#pragma unroll
    for (int k = 0; k < 4; k++) {
        float v = t[tx][ty + k * 8];
        long long o = (long long)(n0 + ty + k * 8) * CCH + c0 + tx;
        bf16 h = __float2bfloat16(v);
        hb[o] = h;
        lb[o] = __float2bfloat16(v - __bfloat162float(h));
    }
}

// ---------------- 2x2x2 maxpool + split; g transposed to (b,256,1600) ----------------
__global__ void pool_kernel(const float* __restrict__ gfull, const float* __restrict__ pfull,
                            bf16* __restrict__ gThi, bf16* __restrict__ gTlo,
                            bf16* __restrict__ phphi, bf16* __restrict__ phplo)
{
    const int m = blockIdx.x;      // 0..1567
    const int b = blockIdx.y;
    const int ci = threadIdx.x;    // 0..255
    const int tp = m / 196;
    const int r = m % 196;
    const int hp = r / 14;
    const int wp = r % 14;
    const float* gb = gfull + (long long)b * NN * CIn;
    const float* pb = pfull + (long long)b * NN * CIn;
    float gm = -1e30f, pm = -1e30f;
#pragma unroll
    for (int dt = 0; dt < 2; dt++)
#pragma unroll
        for (int dh = 0; dh < 2; dh++)
#pragma unroll
            for (int dw = 0; dw < 2; dw++) {
                const long long n = (long long)(2 * tp + dt) * 784 + (2 * hp + dh) * 28 + (2 * wp + dw);
                gm = fmaxf(gm, gb[n * CIn + ci]);
                pm = fmaxf(pm, pb[n * CIn + ci]);
            }
    {
        long long o = ((long long)b * MP_F + m) * CIn + ci;
        bf16 h = __float2bfloat16(pm);
        phphi[o] = h;
        phplo[o] = __float2bfloat16(pm - __bfloat162float(h));
    }
    {
        long long o = ((long long)b * CIn + ci) * MP_Y + m;
        bf16 h = __float2bfloat16(gm);
        gThi[o] = h;
        gTlo[o] = __float2bfloat16(gm - __bfloat162float(h));
    }
}

// ---------------- softmax row (1568 of 1664) -> p hi/lo (1600, zero pad) ----------------
__global__ void softmax_kernel(const float* __restrict__ f, bf16* __restrict__ phi_,
                               bf16* __restrict__ plo_)
{
    const long long row = blockIdx.x;
    const float* p = f + row * MP_F;
    bf16* oh = phi_ + row * MP_Y;
    bf16* ol = plo_ + row * MP_Y;
    const int tid = threadIdx.x;
    __shared__ float red[128];

    float mx = -1e30f;
    for (int i = tid; i < MMr; i += 128) mx = fmaxf(mx, p[i]);
    red[tid] = mx;
    __syncthreads();
    for (int s = 64; s > 0; s >>= 1) {
        if (tid < s) red[tid] = fmaxf(red[tid], red[tid + s]);
        __syncthreads();
    }
    mx = red[0];
    __syncthreads();

    float sum = 0.f;
    for (int i = tid; i < MMr; i += 128) sum += __expf(p[i] - mx);
    red[tid] = sum;
    __syncthreads();
    for (int s = 64; s > 0; s >>= 1) {
        if (tid < s) red[tid] += red[tid + s];
        __syncthreads();
    }
    const float inv = 1.f / red[0];

    for (int i = tid; i < MMr; i += 128) {
        float v = __expf(p[i] - mx) * inv;
        bf16 h = __float2bfloat16(v);
        oh[i] = h;
        ol[i] = __float2bfloat16(v - __bfloat162float(h));
    }
    if (tid < MP_Y - MMr) {
        oh[MMr + tid] = __ushort_as_bfloat16(0);
        ol[MMr + tid] = __ushort_as_bfloat16(0);
    }
}

// ---------------- BN stats: partial sums then finalize ----------------
__global__ void stats_part(const float* __restrict__ wy, float* __restrict__ part)
{
    const int c = blockIdx.x * 128 + threadIdx.x;
    const int rb = blockIdx.y;                      // 98 row blocks of 512 rows
    const float* p = wy + (long long)rb * 512 * CCH + c;
    float s = 0.f, ss = 0.f;
    for (int r = 0; r < 512; r++) {
        float v = p[(long long)r * CCH];
        s += v;
        ss += v * v;
    }
    part[(long long)rb * 1024 + c] = s;
    part[(long long)rb * 1024 + 512 + c] = ss;
}

__global__ void stats_fin(const float* __restrict__ part, float* __restrict__ stats)
{
    const int c = threadIdx.x;   // 512
    float s = 0.f, ss = 0.f;
    for (int r = 0; r < 98; r++) {
        s += part[r * 1024 + c];
        ss += part[r * 1024 + 512 + c];
    }
    const float cnt = (float)BB * (float)NN;
    const float mean = s / cnt;
    const float var = ss / cnt - mean * mean;
    stats[c] = mean;
    stats[CCH + c] = rsqrtf(var + EPS);
}

// ---------------- final: transpose wy (b,n,c)->(b,c,n), BN affine + residual ----------------
__global__ void final_kernel(const float* __restrict__ wy, const float* __restrict__ x,
                             const float* __restrict__ gamma, const float* __restrict__ beta,
                             const float* __restrict__ stats, float* __restrict__ out)
{
    __shared__ float t[32][33];
    const int b = blockIdx.z;
    const int n0 = blockIdx.x * 32;
    const int c0 = blockIdx.y * 32;
    const int tx = threadIdx.x, ty = threadIdx.y;
    const float* wb = wy + (long long)b * NN * CCH;
#pragma unroll
    for (int k = 0; k < 4; k++)
        t[ty + k * 8][tx] = wb[(long long)(n0 + ty + k * 8) * CCH + c0 + tx];
    __syncthreads();
#pragma unroll
    for (int k = 0; k < 4; k++) {
        const int c = c0 + ty + k * 8;
        const float mean = stats[c];
        const float rstd = stats[CCH + c];
        const float gs = gamma[c] * rstd;
        const float off = beta[c] - mean * gs;
        const long long o = ((long long)b * CCH + c) * NN + n0 + tx;
        out[o] = t[tx][ty + k * 8] * gs + off + x[o];
    }
}

// ---------------- launch ----------------
extern "C" void kernel_launch(void* const* d_in, const int* in_sizes, int n_in,
                              void* d_out, int out_size)
{
    const float* x       = (const float*)d_in[0];
    const float* g_w     = (const float*)d_in[1];
    const float* g_b     = (const float*)d_in[2];
    const float* theta_w = (const float*)d_in[3];
    const float* theta_b = (const float*)d_in[4];
    const float* phi_w   = (const float*)d_in[5];
    const float* phi_b   = (const float*)d_in[6];
    const float* W_w     = (const float*)d_in[7];
    // d_in[8] = W_b: constant channel bias cancels exactly in training-mode BN — skipped.
    const float* gamma   = (const float*)d_in[9];
    const float* beta    = (const float*)d_in[10];
    float* out = (float*)d_out;

    unsigned char* S = nullptr;
    float* stats = nullptr;
    cudaGetSymbolAddress((void**)&S, d_scratch);
    cudaGetSymbolAddress((void**)&stats, d_stats);

    bf16* xt_hi  = (bf16*)(S + XT_HI);
    bf16* xt_lo  = (bf16*)(S + XT_LO);
    float* gfull = (float*)(S + GFULL);
    float* pfull = (float*)(S + PHIFULL);
    float* f     = (float*)(S + F_OFF);
    bf16* th_hi  = (bf16*)(S + TH_HI);
    bf16* th_lo  = (bf16*)(S + TH_LO);
    bf16* gt_hi  = (bf16*)(S + GT_HI);
    bf16* gt_lo  = (bf16*)(S + GT_LO);
    bf16* php_hi = (bf16*)(S + PHP_HI);
    bf16* php_lo = (bf16*)(S + PHP_LO);
    bf16* p_hi   = (bf16*)(S + P_HI);
    bf16* p_lo   = (bf16*)(S + P_LO);
    bf16* y_hi   = (bf16*)(S + Y_HI);
    bf16* y_lo   = (bf16*)(S + Y_LO);
    float* wy    = (float*)(S + WY_OFF);
    bf16* thw_hi = (bf16*)(S + W8_OFF + 0);
    bf16* thw_lo = (bf16*)(S + W8_OFF + 262144);
    bf16* phw_hi = (bf16*)(S + W8_OFF + 524288);
    bf16* phw_lo = (bf16*)(S + W8_OFF + 786432);
    bf16* gw_hi  = (bf16*)(S + W8_OFF + 1048576);
    bf16* gw_lo  = (bf16*)(S + W8_OFF + 1310720);
    bf16* ww_hi  = (bf16*)(S + W8_OFF + 1572864);
    bf16* ww_lo  = (bf16*)(S + W8_OFF + 1835008);
    float* part  = (float*)(S + PART_OFF);

    const int smem = 65536;   // 2 stages x (16KB A + 16KB B)
    cudaFuncSetAttribute(tgemm<0>, cudaFuncAttributeMaxDynamicSharedMemorySize, smem);
    cudaFuncSetAttribute(tgemm<1>, cudaFuncAttributeMaxDynamicSharedMemorySize, smem);

    // weight splits (131072 elems each)
    split_kernel<<<512, 256>>>(theta_w, thw_hi, thw_lo, 131072);
    split_kernel<<<512, 256>>>(phi_w,   phw_hi, phw_lo, 131072);
    split_kernel<<<512, 256>>>(g_w,     gw_hi,  gw_lo,  131072);
    split_kernel<<<512, 256>>>(W_w,     ww_hi,  ww_lo,  131072);

    // zero gT + php regions (covers pad rows/cols)
    zero_kernel<<<2048, 256>>>((float4*)(S + GT_HI), 13369344 / 16);

    // transpose + split x -> xT (b, n, 512)
    xpose_kernel<<<dim3(NN / 32, CCH / 32, BB), dim3(32, 8)>>>(x, xt_hi, xt_lo);

    const long long sXT = (long long)NN * CCH;
    const long long sCI = (long long)NN * CIn;

    // theta conv -> bf16 planes (b, n, 256)
    tgemm<1><<<dim3(98, 2, BB), 256, smem>>>(xt_hi, xt_lo, thw_hi, thw_lo,
        nullptr, th_hi, th_lo, theta_b, CCH, CIn, sXT, 0LL, sCI);
    // g conv -> gfull fp32 (b, n, 256)
    tgemm<0><<<dim3(98, 2, BB), 256, smem>>>(xt_hi, xt_lo, gw_hi, gw_lo,
        gfull, nullptr, nullptr, g_b, CCH, CIn, sXT, 0LL, sCI);
    // phi conv -> pfull fp32 (b, n, 256)
    tgemm<0><<<dim3(98, 2, BB), 256, smem>>>(xt_hi, xt_lo, phw_hi, phw_lo,
        pfull, nullptr, nullptr, phi_b, CCH, CIn, sXT, 0LL, sCI);

    // pool + split: gT (b,256,1600), php (b,1664,256)
    pool_kernel<<<dim3(MMr, BB), 256>>>(gfull, pfull, gt_hi, gt_lo, php_hi, php_lo);

    // f = theta @ phi^T : (b, n, 1664) fp32
    tgemm<0><<<dim3(98, MP_F / 128, BB), 256, smem>>>(th_hi, th_lo, php_hi, php_lo,
        f, nullptr, nullptr, nullptr, CIn, MP_F, sCI, (long long)MP_F * CIn,
        (long long)NN * MP_F);

    // softmax -> p hi/lo (b, n, 1600)
    softmax_kernel<<<BB * NN, 128>>>(f, p_hi, p_lo);

    // y = p @ gT^T : (b, n, 256) bf16 planes
    tgemm<1><<<dim3(98, 2, BB), 256, smem>>>(p_hi, p_lo, gt_hi, gt_lo,
        nullptr, y_hi, y_lo, nullptr, MP_Y, CIn, (long long)NN * MP_Y,
        (long long)CIn * MP_Y, sCI);

    // wy = y @ W_w^T : (b, n, 512) fp32  (W_b dropped: cancels in BN)
    tgemm<0><<<dim3(98, 4, BB), 256, smem>>>(y_hi, y_lo, ww_hi, ww_lo,
        wy, nullptr, nullptr, nullptr, CIn, CCH, sCI, 0LL, (long long)NN * CCH);

    // BN stats
    stats_part<<<dim3(4, 98), 128>>>(wy, part);
    stats_fin<<<1, 512>>>(part, stats);

    // transpose + BN affine + residual
    final_kernel<<<dim3(NN / 32, CCH / 32, BB), dim3(32, 8)>>>(wy, x, gamma, beta, stats, out);
}

// round 6
// speedup vs baseline: 1.8335x; 1.5075x over previous
#include <cuda_runtime.h>
#include <cuda_bf16.h>
#include <stdint.h>
#include <math.h>

typedef __nv_bfloat16 bf16;
typedef unsigned int u32;

// ---------------- problem constants ----------------
#define BB 4
#define CCH 512
#define CIn 256
#define NN 12544
#define MMr 1568          // real pooled positions
#define MP_Y 1600         // pad for y-GEMM K (25*64)
#define MP_F 1664         // pad for f-GEMM N (13*128)
#define EPS 1e-5f

// ---------------- scratch layout (byte offsets) ----------------
#define XT_HI   0ULL
#define XT_LO   51380224ULL
#define GFULL   102760448ULL
#define PHIFULL 154140672ULL
#define F_OFF   0ULL            // aliases XT/GFULL/PHIFULL (dead by then)
#define TH_HI   334987264ULL
#define TH_LO   360677376ULL
#define GT_HI   386367488ULL
#define GT_LO   389644288ULL
#define PHP_HI  392921088ULL
#define PHP_LO  396328960ULL
#define P_HI    399736832ULL
#define P_LO    560300032ULL
#define Y_HI    334987264ULL    // alias TH_HI (theta dead after f GEMM)
#define Y_LO    360677376ULL
#define WY_OFF  399736832ULL    // alias P_HI (p dead after y GEMM)
#define W8_OFF  720863232ULL
#define PART_OFF 722960384ULL
#define SCRATCH_BYTES 723400704ULL

__device__ __align__(128) unsigned char d_scratch[SCRATCH_BYTES];
__device__ __align__(16) float d_stats[2 * CCH];

// ---------------- helpers ----------------
__device__ __forceinline__ u32 smem_u32(const void* p) {
    u32 a;
    asm("{ .reg .u64 t; cvta.to.shared.u64 t, %1; cvt.u32.u64 %0, t; }" : "=r"(a) : "l"(p));
    return a;
}
__device__ __forceinline__ void ldsm4(u32& r0, u32& r1, u32& r2, u32& r3, u32 addr) {
    asm volatile("ldmatrix.sync.aligned.m8n8.x4.shared.b16 {%0,%1,%2,%3}, [%4];"
                 : "=r"(r0), "=r"(r1), "=r"(r2), "=r"(r3) : "r"(addr));
}
__device__ __forceinline__ void mma16816(float* d, const u32* a, const u32* b) {
    asm volatile(
        "mma.sync.aligned.m16n8k16.row.col.f32.bf16.bf16.f32 "
        "{%0,%1,%2,%3},{%4,%5,%6,%7},{%8,%9},{%0,%1,%2,%3};"
        : "+f"(d[0]), "+f"(d[1]), "+f"(d[2]), "+f"(d[3])
        : "r"(a[0]), "r"(a[1]), "r"(a[2]), "r"(a[3]), "r"(b[0]), "r"(b[1]));
}
__device__ __forceinline__ u32 sw128(u32 off) { return off ^ ((off >> 3) & 0x70); }
__device__ __forceinline__ void cp16(u32 dst, const void* src) {
    asm volatile("cp.async.cg.shared.global [%0], [%1], 16;" :: "r"(dst), "l"(src));
}
#define CP_COMMIT() asm volatile("cp.async.commit_group;" ::: "memory")
#define CP_WAIT1()  asm volatile("cp.async.wait_group 1;" ::: "memory")

// ---------------- cp.async split-bf16 GEMM ----------------
// D = A_hi*B_hi^T + A_lo*B_hi^T + A_hi*B_lo^T  (3 K-passes, fp32 accum)
// A planes: (Mtot x K) bf16 row-major. B planes: (Ntot x K) bf16 row-major.
// CTA tile 128x128, BK=64, 8 warps (2M x 4N), 3-stage cp.async ring, 2 CTAs/SM.
// EPI 0: fp32 C row-major + optional col bias. EPI 1: bf16 hi/lo planes.
template <int EPI>
__global__ __launch_bounds__(256, 2)
void tgemm(const bf16* __restrict__ Ahi, const bf16* __restrict__ Alo,
           const bf16* __restrict__ Bhi, const bf16* __restrict__ Blo,
           float* __restrict__ Cf, bf16* __restrict__ Chi, bf16* __restrict__ Clo,
           const float* __restrict__ bias,
           int K, int ldc, long long sA, long long sB, long long sC)
{
    extern __shared__ __align__(1024) unsigned char sm[];
    const u32 sbase = smem_u32(sm);
    const int tid = threadIdx.x;
    const int wid = tid >> 5;
    const int lane = tid & 31;
    const int m0 = blockIdx.x * 128;
    const int n0 = blockIdx.y * 128;
    const long long bz = blockIdx.z;
    Ahi += bz * sA; Alo += bz * sA;
    Bhi += bz * sB; Blo += bz * sB;

    const int Kc = K >> 6;
    const int total = 3 * Kc;

    // ---- cp.async mapping: thread -> row (tid>>1), 4 x 16B chunks ----
    const int rowL = tid >> 1;
    const int segb = (tid & 1) * 32;     // element offset within 64-elem row
    const long long gA = (long long)(m0 + rowL) * K + segb;
    const long long gB = (long long)(n0 + rowL) * K + segb;
    u32 soff[4];
#pragma unroll
    for (int i = 0; i < 4; i++)
        soff[i] = sw128((u32)rowL * 128 + (u32)segb * 2 + i * 16);

#define ISSUE(it2) do { \
    const int _p = (it2) / Kc; \
    const int _k0 = ((it2) - _p * Kc) << 6; \
    const bf16* _A = (_p == 1) ? Alo : Ahi; \
    const bf16* _B = (_p == 2) ? Blo : Bhi; \
    const u32 _sa = sbase + ((it2) % 3) * 32768u; \
    const u32 _sb = _sa + 16384u; \
    _Pragma("unroll") \
    for (int _i = 0; _i < 4; _i++) { \
        cp16(_sa + soff[_i], _A + gA + _k0 + _i * 8); \
        cp16(_sb + soff[_i], _B + gB + _k0 + _i * 8); \
    } \
} while (0)

    // ---- per-lane ldmatrix bases ----
    const int wm = wid >> 2;
    const int wn = wid & 3;
    const int rowA = wm * 64 + ((lane >> 3) & 1) * 8 + (lane & 7);
    const u32 kbA = (u32)(lane >> 4) * 16;
    const int rowB = wn * 32 + ((lane >> 4) & 1) * 8 + (lane & 7);
    const u32 kbB = (u32)((lane >> 3) & 1) * 16;

    float acc[4][4][4];
#pragma unroll
    for (int mt = 0; mt < 4; mt++)
#pragma unroll
        for (int nt = 0; nt < 4; nt++)
#pragma unroll
            for (int q = 0; q < 4; q++) acc[mt][nt][q] = 0.f;

    // prologue: stages 0,1
    ISSUE(0); CP_COMMIT();
    ISSUE(1); CP_COMMIT();

    for (int it = 0; it < total; it++) {
        CP_WAIT1();
        __syncthreads();
        // refill freed stage (safe: all warps past compute(it-1) due to sync)
        if (it + 2 < total) ISSUE(it + 2);
        CP_COMMIT();

        const u32 sA32 = sbase + (it % 3) * 32768u;
        const u32 sB32 = sA32 + 16384u;
#pragma unroll
        for (int kk = 0; kk < 4; kk++) {
            u32 af[4][4];
#pragma unroll
            for (int mt = 0; mt < 4; mt++) {
                u32 off = (u32)(rowA + mt * 16) * 128 + (u32)kk * 32 + kbA;
                ldsm4(af[mt][0], af[mt][1], af[mt][2], af[mt][3], sA32 + sw128(off));
            }
            u32 bfr[2][4];
#pragma unroll
            for (int nt2 = 0; nt2 < 2; nt2++) {
                u32 off = (u32)(rowB + nt2 * 16) * 128 + (u32)kk * 32 + kbB;
                ldsm4(bfr[nt2][0], bfr[nt2][1], bfr[nt2][2], bfr[nt2][3], sB32 + sw128(off));
            }
#pragma unroll
            for (int mt = 0; mt < 4; mt++)
#pragma unroll
                for (int nt = 0; nt < 4; nt++)
                    mma16816(acc[mt][nt], af[mt], &bfr[nt >> 1][(nt & 1) * 2]);
        }
    }
#undef ISSUE

    // ---- epilogue ----
    const int r0 = m0 + wm * 64 + (lane >> 2);
    const int cb0 = n0 + wn * 32 + (lane & 3) * 2;
#pragma unroll
    for (int nt = 0; nt < 4; nt++) {
        const int c = cb0 + nt * 8;
        const float b0v = bias ? bias[c] : 0.f;
        const float b1v = bias ? bias[c + 1] : 0.f;
#pragma unroll
        for (int mt = 0; mt < 4; mt++) {
            const long long ra = r0 + mt * 16;
            const long long rb = ra + 8;
            float v0 = acc[mt][nt][0] + b0v;
            float v1 = acc[mt][nt][1] + b1v;
            float v2 = acc[mt][nt][2] + b0v;
            float v3 = acc[mt][nt][3] + b1v;
            if (EPI == 0) {
                float* base = Cf + bz * sC;
                *(float2*)(base + ra * ldc + c) = make_float2(v0, v1);
                *(float2*)(base + rb * ldc + c) = make_float2(v2, v3);
            } else {
                bf16 h0 = __float2bfloat16(v0), h1 = __float2bfloat16(v1);
                bf16 h2 = __float2bfloat16(v2), h3 = __float2bfloat16(v3);
                bf16 l0 = __float2bfloat16(v0 - __bfloat162float(h0));
                bf16 l1 = __float2bfloat16(v1 - __bfloat162float(h1));
                bf16 l2 = __float2bfloat16(v2 - __bfloat162float(h2));
                bf16 l3 = __float2bfloat16(v3 - __bfloat162float(h3));
                bf16* hb = Chi + bz * sC;
                bf16* lb = Clo + bz * sC;
                *(u32*)(hb + ra * ldc + c) = (u32)__bfloat16_as_ushort(h0) | ((u32)__bfloat16_as_ushort(h1) << 16);
                *(u32*)(hb + rb * ldc + c) = (u32)__bfloat16_as_ushort(h2) | ((u32)__bfloat16_as_ushort(h3) << 16);
                *(u32*)(lb + ra * ldc + c) = (u32)__bfloat16_as_ushort(l0) | ((u32)__bfloat16_as_ushort(l1) << 16);
                *(u32*)(lb + rb * ldc + c) = (u32)__bfloat16_as_ushort(l2) | ((u32)__bfloat16_as_ushort(l3) << 16);
            }
        }
    }
}

// ---------------- fp32 -> bf16 hi/lo split ----------------
__global__ void split_kernel(const float* __restrict__ src, bf16* __restrict__ hi,
                             bf16* __restrict__ lo, int n)
{
    int i = blockIdx.x * 256 + threadIdx.x;
    if (i < n) {
        float v = src[i];
        bf16 h = __float2bfloat16(v);
        hi[i] = h;
        lo[i] = __float2bfloat16(v - __bfloat162float(h));
    }
}

// ---------------- zero fill ----------------
__global__ void zero_kernel(float4* __restrict__ p, long long n4)
{
    long long i = (long long)blockIdx.x * 256 + threadIdx.x;
    const long long stride = (long long)gridDim.x * 256;
    for (; i < n4; i += stride) p[i] = make_float4(0.f, 0.f, 0.f, 0.f);
}

// ---------------- transpose x (b,512,N) -> xT hi/lo (b,N,512) ----------------
__global__ void xpose_kernel(const float* __restrict__ x, bf16* __restrict__ xhi,
                             bf16* __restrict__ xlo)
{
    __shared__ float t[32][33];
    const int b = blockIdx.z;
    const int n0 = blockIdx.x * 32;
    const int c0 = blockIdx.y * 32;
    const int tx = threadIdx.x, ty = threadIdx.y;
    const float* xb = x + (long long)b * CCH * NN;
#pragma unroll
    for (int k = 0; k < 4; k++)
        t[ty + k * 8][tx] = xb[(long long)(c0 + ty + k * 8) * NN + n0 + tx];
    __syncthreads();
    bf16* hb = xhi + (long long)b * NN * CCH;
    bf16* lb = xlo + (long long)b * NN * CCH;
#pragma unroll
    for (int k = 0; k < 4; k++) {
        float v = t[tx][ty + k * 8];
        long long o = (long long)(n0 + ty + k * 8) * CCH + c0 + tx;
        bf16 h = __float2bfloat16(v);
        hb[o] = h;
        lb[o] = __float2bfloat16(v - __bfloat162float(h));
    }
}

// ---------------- 2x2x2 maxpool + split; g transposed to (b,256,1600) ----------------
__global__ void pool_kernel(const float* __restrict__ gfull, const float* __restrict__ pfull,
                            bf16* __restrict__ gThi, bf16* __restrict__ gTlo,
                            bf16* __restrict__ phphi, bf16* __restrict__ phplo)
{
    const int m = blockIdx.x;      // 0..1567
    const int b = blockIdx.y;
    const int ci = threadIdx.x;    // 0..255
    const int tp = m / 196;
    const int r = m % 196;
    const int hp = r / 14;
    const int wp = r % 14;
    const float* gb = gfull + (long long)b * NN * CIn;
    const float* pb = pfull + (long long)b * NN * CIn;
    float gm = -1e30f, pm = -1e30f;
#pragma unroll
    for (int dt = 0; dt < 2; dt++)
#pragma unroll
        for (int dh = 0; dh < 2; dh++)
#pragma unroll
            for (int dw = 0; dw < 2; dw++) {
                const long long n = (long long)(2 * tp + dt) * 784 + (2 * hp + dh) * 28 + (2 * wp + dw);
                gm = fmaxf(gm, gb[n * CIn + ci]);
                pm = fmaxf(pm, pb[n * CIn + ci]);
            }
    {
        long long o = ((long long)b * MP_F + m) * CIn + ci;
        bf16 h = __float2bfloat16(pm);
        phphi[o] = h;
        phplo[o] = __float2bfloat16(pm - __bfloat162float(h));
    }
    {
        long long o = ((long long)b * CIn + ci) * MP_Y + m;
        bf16 h = __float2bfloat16(gm);
        gThi[o] = h;
        gTlo[o] = __float2bfloat16(gm - __bfloat162float(h));
    }
}

// ---------------- softmax: single global read via smem row cache ----------------
__global__ __launch_bounds__(256)
void softmax_kernel(const float* __restrict__ f, bf16* __restrict__ phi_,
                    bf16* __restrict__ plo_)
{
    __shared__ float row[MMr];
    __shared__ float red[8];
    const long long r = blockIdx.x;
    const float* p = f + r * MP_F;
    bf16* oh = phi_ + r * MP_Y;
    bf16* ol = plo_ + r * MP_Y;
    const int tid = threadIdx.x;
    const int wid = tid >> 5, lane = tid & 31;

    float mx = -1e30f;
    for (int i = tid; i < MMr; i += 256) {
        float v = p[i];
        row[i] = v;
        mx = fmaxf(mx, v);
    }
#pragma unroll
    for (int s = 16; s > 0; s >>= 1) mx = fmaxf(mx, __shfl_xor_sync(~0u, mx, s));
    if (lane == 0) red[wid] = mx;
    __syncthreads();
    {
        float t = red[lane & 7];
#pragma unroll
        for (int s = 4; s > 0; s >>= 1) t = fmaxf(t, __shfl_xor_sync(~0u, t, s));
        mx = t;
    }

    float sum = 0.f;
    for (int i = tid; i < MMr; i += 256) {
        float e = __expf(row[i] - mx);
        row[i] = e;
        sum += e;
    }
#pragma unroll
    for (int s = 16; s > 0; s >>= 1) sum += __shfl_xor_sync(~0u, sum, s);
    __syncthreads();
    if (lane == 0) red[wid] = sum;
    __syncthreads();
    {
        float t = red[lane & 7];
#pragma unroll
        for (int s = 4; s > 0; s >>= 1) t += __shfl_xor_sync(~0u, t, s);
        sum = t;
    }
    const float inv = 1.f / sum;

    for (int i = tid; i < MMr; i += 256) {
        float v = row[i] * inv;
        bf16 h = __float2bfloat16(v);
        oh[i] = h;
        ol[i] = __float2bfloat16(v - __bfloat162float(h));
    }
    if (tid < MP_Y - MMr) {
        oh[MMr + tid] = __ushort_as_bfloat16(0);
        ol[MMr + tid] = __ushort_as_bfloat16(0);
    }
}

// ---------------- BN stats: partial sums then finalize ----------------
__global__ void stats_part(const float* __restrict__ wy, float* __restrict__ part)
{
    const int c = blockIdx.x * 128 + threadIdx.x;
    const int rb = blockIdx.y;                      // 98 row blocks of 512 rows
    const float* p = wy + (long long)rb * 512 * CCH + c;
    float s = 0.f, ss = 0.f;
    for (int r = 0; r < 512; r++) {
        float v = p[(long long)r * CCH];
        s += v;
        ss += v * v;
    }
    part[(long long)rb * 1024 + c] = s;
    part[(long long)rb * 1024 + 512 + c] = ss;
}

__global__ void stats_fin(const float* __restrict__ part, float* __restrict__ stats)
{
    const int c = threadIdx.x;   // 512
    float s = 0.f, ss = 0.f;
    for (int r = 0; r < 98; r++) {
        s += part[r * 1024 + c];
        ss += part[r * 1024 + 512 + c];
    }
    const float cnt = (float)BB * (float)NN;
    const float mean = s / cnt;
    const float var = ss / cnt - mean * mean;
    stats[c] = mean;
    stats[CCH + c] = rsqrtf(var + EPS);
}

// ---------------- final: transpose wy (b,n,c)->(b,c,n), BN affine + residual ----------------
__global__ void final_kernel(const float* __restrict__ wy, const float* __restrict__ x,
                             const float* __restrict__ gamma, const float* __restrict__ beta,
                             const float* __restrict__ stats, float* __restrict__ out)
{
    __shared__ float t[32][33];
    const int b = blockIdx.z;
    const int n0 = blockIdx.x * 32;
    const int c0 = blockIdx.y * 32;
    const int tx = threadIdx.x, ty = threadIdx.y;
    const float* wb = wy + (long long)b * NN * CCH;
#pragma unroll
    for (int k = 0; k < 4; k++)
        t[ty + k * 8][tx] = wb[(long long)(n0 + ty + k * 8) * CCH + c0 + tx];
    __syncthreads();
#pragma unroll
    for (int k = 0; k < 4; k++) {
        const int c = c0 + ty + k * 8;
        const float mean = stats[c];
        const float rstd = stats[CCH + c];
        const float gs = gamma[c] * rstd;
        const float off = beta[c] - mean * gs;
        const long long o = ((long long)b * CCH + c) * NN + n0 + tx;
        out[o] = t[tx][ty + k * 8] * gs + off + x[o];
    }
}

// ---------------- launch ----------------
extern "C" void kernel_launch(void* const* d_in, const int* in_sizes, int n_in,
                              void* d_out, int out_size)
{
    const float* x       = (const float*)d_in[0];
    const float* g_w     = (const float*)d_in[1];
    const float* g_b     = (const float*)d_in[2];
    const float* theta_w = (const float*)d_in[3];
    const float* theta_b = (const float*)d_in[4];
    const float* phi_w   = (const float*)d_in[5];
    const float* phi_b   = (const float*)d_in[6];
    const float* W_w     = (const float*)d_in[7];
    // d_in[8] = W_b: constant channel bias cancels exactly in training-mode BN — skipped.
    const float* gamma   = (const float*)d_in[9];
    const float* beta    = (const float*)d_in[10];
    float* out = (float*)d_out;

    unsigned char* S = nullptr;
    float* stats = nullptr;
    cudaGetSymbolAddress((void**)&S, d_scratch);
    cudaGetSymbolAddress((void**)&stats, d_stats);

    bf16* xt_hi  = (bf16*)(S + XT_HI);
    bf16* xt_lo  = (bf16*)(S + XT_LO);
    float* gfull = (float*)(S + GFULL);
    float* pfull = (float*)(S + PHIFULL);
    float* f     = (float*)(S + F_OFF);
    bf16* th_hi  = (bf16*)(S + TH_HI);
    bf16* th_lo  = (bf16*)(S + TH_LO);
    bf16* gt_hi  = (bf16*)(S + GT_HI);
    bf16* gt_lo  = (bf16*)(S + GT_LO);
    bf16* php_hi = (bf16*)(S + PHP_HI);
    bf16* php_lo = (bf16*)(S + PHP_LO);
    bf16* p_hi   = (bf16*)(S + P_HI);
    bf16* p_lo   = (bf16*)(S + P_LO);
    bf16* y_hi   = (bf16*)(S + Y_HI);
    bf16* y_lo   = (bf16*)(S + Y_LO);
    float* wy    = (float*)(S + WY_OFF);
    bf16* thw_hi = (bf16*)(S + W8_OFF + 0);
    bf16* thw_lo = (bf16*)(S + W8_OFF + 262144);
    bf16* phw_hi = (bf16*)(S + W8_OFF + 524288);
    bf16* phw_lo = (bf16*)(S + W8_OFF + 786432);
    bf16* gw_hi  = (bf16*)(S + W8_OFF + 1048576);
    bf16* gw_lo  = (bf16*)(S + W8_OFF + 1310720);
    bf16* ww_hi  = (bf16*)(S + W8_OFF + 1572864);
    bf16* ww_lo  = (bf16*)(S + W8_OFF + 1835008);
    float* part  = (float*)(S + PART_OFF);

    const int smem = 3 * 32768;   // 96 KB: 3-stage ring
    cudaFuncSetAttribute(tgemm<0>, cudaFuncAttributeMaxDynamicSharedMemorySize, smem);
    cudaFuncSetAttribute(tgemm<1>, cudaFuncAttributeMaxDynamicSharedMemorySize, smem);

    // weight splits (131072 elems each)
    split_kernel<<<512, 256>>>(theta_w, thw_hi, thw_lo, 131072);
    split_kernel<<<512, 256>>>(phi_w,   phw_hi, phw_lo, 131072);
    split_kernel<<<512, 256>>>(g_w,     gw_hi,  gw_lo,  131072);
    split_kernel<<<512, 256>>>(W_w,     ww_hi,  ww_lo,  131072);

    // zero gT + php regions (covers pad rows/cols)
    zero_kernel<<<2048, 256>>>((float4*)(S + GT_HI), 13369344 / 16);

    // transpose + split x -> xT (b, n, 512)
    xpose_kernel<<<dim3(NN / 32, CCH / 32, BB), dim3(32, 8)>>>(x, xt_hi, xt_lo);

    const long long sXT = (long long)NN * CCH;
    const long long sCI = (long long)NN * CIn;

    // theta conv -> bf16 planes (b, n, 256)
    tgemm<1><<<dim3(98, 2, BB), 256, smem>>>(xt_hi, xt_lo, thw_hi, thw_lo,
        nullptr, th_hi, th_lo, theta_b, CCH, CIn, sXT, 0LL, sCI);
    // g conv -> gfull fp32 (b, n, 256)
    tgemm<0><<<dim3(98, 2, BB), 256, smem>>>(xt_hi, xt_lo, gw_hi, gw_lo,
        gfull, nullptr, nullptr, g_b, CCH, CIn, sXT, 0LL, sCI);
    // phi conv -> pfull fp32 (b, n, 256)
    tgemm<0><<<dim3(98, 2, BB), 256, smem>>>(xt_hi, xt_lo, phw_hi, phw_lo,
        pfull, nullptr, nullptr, phi_b, CCH, CIn, sXT, 0LL, sCI);

    // pool + split: gT (b,256,1600), php (b,1664,256)
    pool_kernel<<<dim3(MMr, BB), 256>>>(gfull, pfull, gt_hi, gt_lo, php_hi, php_lo);

    // f = theta @ phi^T : (b, n, 1664) fp32
    tgemm<0><<<dim3(98, MP_F / 128, BB), 256, smem>>>(th_hi, th_lo, php_hi, php_lo,
        f, nullptr, nullptr, nullptr, CIn, MP_F, sCI, (long long)MP_F * CIn,
        (long long)NN * MP_F);

    // softmax -> p hi/lo (b, n, 1600)
    softmax_kernel<<<BB * NN, 256>>>(f, p_hi, p_lo);

    // y = p @ gT^T : (b, n, 256) bf16 planes
    tgemm<1><<<dim3(98, 2, BB), 256, smem>>>(p_hi, p_lo, gt_hi, gt_lo,
        nullptr, y_hi, y_lo, nullptr, MP_Y, CIn, (long long)NN * MP_Y,
        (long long)CIn * MP_Y, sCI);

    // wy = y @ W_w^T : (b, n, 512) fp32  (W_b dropped: cancels in BN)
    tgemm<0><<<dim3(98, 4, BB), 256, smem>>>(y_hi, y_lo, ww_hi, ww_lo,
        wy, nullptr, nullptr, nullptr, CIn, CCH, sCI, 0LL, (long long)NN * CCH);

    // BN stats
    stats_part<<<dim3(4, 98), 128>>>(wy, part);
    stats_fin<<<1, 512>>>(part, stats);

    // transpose + BN affine + residual
    final_kernel<<<dim3(NN / 32, CCH / 32, BB), dim3(32, 8)>>>(wy, x, gamma, beta, stats, out);
}

// round 7
// speedup vs baseline: 1.8905x; 1.0311x over previous
#include <cuda_runtime.h>
#include <cuda_bf16.h>
#include <stdint.h>
#include <math.h>

typedef __nv_bfloat16 bf16;
typedef unsigned int u32;

// ---------------- problem constants ----------------
#define BB 4
#define CCH 512
#define CIn 256
#define NN 12544
#define MMr 1568          // real pooled positions
#define MP_Y 1600         // pad for y-GEMM K (25*64)
#define MP_F 1664         // pad for f-GEMM N (13*128)
#define EPS 1e-5f

// ---------------- scratch layout (byte offsets) ----------------
// lifetimes:
//   xT (0..103MB)         : until convs done
//   f  (0..335MB)         : f-GEMM write .. softmax read (aliases xT after convs)
//   conv planes (335..489): conv write .. f-GEMM (theta) / pool (g,phi)
//   p  (335..656)         : softmax write .. y-GEMM read (aliases conv planes)
//   y  (0..51MB)          : y-GEMM write .. W-GEMM read (aliases f)
//   wy (103..206MB)       : W-GEMM write .. stats/final
//   gt/php (656..670MB)   : pool write .. y-GEMM read
#define XT_HI    0ULL
#define XT_LO    51380224ULL
#define F_OFF    0ULL
#define CONV_HI  334987264ULL
#define CONV_LO  412057600ULL
#define P_HI     334987264ULL
#define P_LO     495550464ULL
#define Y_HI     0ULL
#define Y_LO     25690112ULL
#define WY_OFF   102760448ULL
#define GT_HI    656113664ULL
#define GT_LO    659390464ULL
#define PHP_HI   662667264ULL
#define PHP_LO   666075136ULL
#define W8_OFF   669483008ULL
#define BCAT_OFF 671580160ULL
#define PART_OFF 671583232ULL
#define SCRATCH_BYTES 672000000ULL

#define CONV_PLANE 25690112ULL   // bytes per conv plane (4*NN*256*2)

__device__ __align__(128) unsigned char d_scratch[SCRATCH_BYTES];
__device__ __align__(16) float d_stats[2 * CCH];

// ---------------- helpers ----------------
__device__ __forceinline__ u32 smem_u32(const void* p) {
    u32 a;
    asm("{ .reg .u64 t; cvta.to.shared.u64 t, %1; cvt.u32.u64 %0, t; }" : "=r"(a) : "l"(p));
    return a;
}
__device__ __forceinline__ void ldsm4(u32& r0, u32& r1, u32& r2, u32& r3, u32 addr) {
    asm volatile("ldmatrix.sync.aligned.m8n8.x4.shared.b16 {%0,%1,%2,%3}, [%4];"
                 : "=r"(r0), "=r"(r1), "=r"(r2), "=r"(r3) : "r"(addr));
}
__device__ __forceinline__ void mma16816(float* d, const u32* a, const u32* b) {
    asm volatile(
        "mma.sync.aligned.m16n8k16.row.col.f32.bf16.bf16.f32 "
        "{%0,%1,%2,%3},{%4,%5,%6,%7},{%8,%9},{%0,%1,%2,%3};"
        : "+f"(d[0]), "+f"(d[1]), "+f"(d[2]), "+f"(d[3])
        : "r"(a[0]), "r"(a[1]), "r"(a[2]), "r"(a[3]), "r"(b[0]), "r"(b[1]));
}
__device__ __forceinline__ u32 sw128(u32 off) { return off ^ ((off >> 3) & 0x70); }
__device__ __forceinline__ void cp16(u32 dst, const void* src) {
    asm volatile("cp.async.cg.shared.global [%0], [%1], 16;" :: "r"(dst), "l"(src));
}
#define CP_COMMIT() asm volatile("cp.async.commit_group;" ::: "memory")
#define CP_WAIT1()  asm volatile("cp.async.wait_group 1;" ::: "memory")

// ---------------- cp.async split-bf16 GEMM ----------------
// D = A_hi*B_hi^T + A_hi*B_lo^T + A_lo*B_hi^T  (3 K-passes; A_hi passes adjacent for L2 reuse)
// A planes: (Mtot x K) bf16 row-major. B planes: (Ntot x K) bf16 row-major.
// CTA tile 128x128, BK=64, 8 warps (2M x 4N), 3-stage cp.async ring, 2 CTAs/SM.
// EPI 0: fp32 C row-major + optional col bias. EPI 1: bf16 hi/lo planes.
// SEG 1: output tensor is segmented in 256-col groups (fused conv): plane =
//        base + (n0>>8)*segS, local col = c & 255; bias indexed by global c.
template <int EPI, int SEG>
__global__ __launch_bounds__(256, 2)
void tgemm(const bf16* __restrict__ Ahi, const bf16* __restrict__ Alo,
           const bf16* __restrict__ Bhi, const bf16* __restrict__ Blo,
           float* __restrict__ Cf, bf16* __restrict__ Chi, bf16* __restrict__ Clo,
           const float* __restrict__ bias,
           int K, int ldc, long long sA, long long sB, long long sC, long long segS)
{
    extern __shared__ __align__(1024) unsigned char sm[];
    const u32 sbase = smem_u32(sm);
    const int tid = threadIdx.x;
    const int wid = tid >> 5;
    const int lane = tid & 31;
    const int m0 = blockIdx.x * 128;
    const int n0 = blockIdx.y * 128;
    const long long bz = blockIdx.z;
    Ahi += bz * sA; Alo += bz * sA;
    Bhi += bz * sB; Blo += bz * sB;

    const int Kc = K >> 6;
    const int total = 3 * Kc;

    // ---- cp.async mapping: thread -> row (tid>>1), 4 x 16B chunks ----
    const int rowL = tid >> 1;
    const int segb = (tid & 1) * 32;     // element offset within 64-elem row
    const long long gA = (long long)(m0 + rowL) * K + segb;
    const long long gB = (long long)(n0 + rowL) * K + segb;
    u32 soff[4];
#pragma unroll
    for (int i = 0; i < 4; i++)
        soff[i] = sw128((u32)rowL * 128 + (u32)segb * 2 + i * 16);

// pass order: 0 = hi*hi, 1 = hi*lo, 2 = lo*hi (A_hi reused in passes 0,1)
#define ISSUE(it2) do { \
    const int _p = (it2) / Kc; \
    const int _k0 = ((it2) - _p * Kc) << 6; \
    const bf16* _A = (_p == 2) ? Alo : Ahi; \
    const bf16* _B = (_p == 1) ? Blo : Bhi; \
    const u32 _sa = sbase + ((it2) % 3) * 32768u; \
    const u32 _sb = _sa + 16384u; \
    _Pragma("unroll") \
    for (int _i = 0; _i < 4; _i++) { \
        cp16(_sa + soff[_i], _A + gA + _k0 + _i * 8); \
        cp16(_sb + soff[_i], _B + gB + _k0 + _i * 8); \
    } \
} while (0)

    // ---- per-lane ldmatrix bases ----
    const int wm = wid >> 2;
    const int wn = wid & 3;
    const int rowA = wm * 64 + ((lane >> 3) & 1) * 8 + (lane & 7);
    const u32 kbA = (u32)(lane >> 4) * 16;
    const int rowB = wn * 32 + ((lane >> 4) & 1) * 8 + (lane & 7);
    const u32 kbB = (u32)((lane >> 3) & 1) * 16;

    float acc[4][4][4];
#pragma unroll
    for (int mt = 0; mt < 4; mt++)
#pragma unroll
        for (int nt = 0; nt < 4; nt++)
#pragma unroll
            for (int q = 0; q < 4; q++) acc[mt][nt][q] = 0.f;

    // prologue: stages 0,1
    ISSUE(0); CP_COMMIT();
    ISSUE(1); CP_COMMIT();

    for (int it = 0; it < total; it++) {
        CP_WAIT1();
        __syncthreads();
        // refill freed stage (safe: all warps past compute(it-1) due to sync)
        if (it + 2 < total) ISSUE(it + 2);
        CP_COMMIT();

        const u32 sA32 = sbase + (it % 3) * 32768u;
        const u32 sB32 = sA32 + 16384u;
#pragma unroll
        for (int kk = 0; kk < 4; kk++) {
            u32 af[4][4];
#pragma unroll
            for (int mt = 0; mt < 4; mt++) {
                u32 off = (u32)(rowA + mt * 16) * 128 + (u32)kk * 32 + kbA;
                ldsm4(af[mt][0], af[mt][1], af[mt][2], af[mt][3], sA32 + sw128(off));
            }
            u32 bfr[2][4];
#pragma unroll
            for (int nt2 = 0; nt2 < 2; nt2++) {
                u32 off = (u32)(rowB + nt2 * 16) * 128 + (u32)kk * 32 + kbB;
                ldsm4(bfr[nt2][0], bfr[nt2][1], bfr[nt2][2], bfr[nt2][3], sB32 + sw128(off));
            }
#pragma unroll
            for (int mt = 0; mt < 4; mt++)
#pragma unroll
                for (int nt = 0; nt < 4; nt++)
                    mma16816(acc[mt][nt], af[mt], &bfr[nt >> 1][(nt & 1) * 2]);
        }
    }
#undef ISSUE

    // ---- epilogue ----
    const int r0 = m0 + wm * 64 + (lane >> 2);
    const int cb0 = n0 + wn * 32 + (lane & 3) * 2;
    const long long obase = bz * sC + (SEG ? (long long)(n0 >> 8) * segS : 0LL);
#pragma unroll
    for (int nt = 0; nt < 4; nt++) {
        const int c = cb0 + nt * 8;
        const int cl = SEG ? (c & 255) : c;
        const float b0v = bias ? bias[c] : 0.f;
        const float b1v = bias ? bias[c + 1] : 0.f;
#pragma unroll
        for (int mt = 0; mt < 4; mt++) {
            const long long ra = r0 + mt * 16;
            const long long rb = ra + 8;
            float v0 = acc[mt][nt][0] + b0v;
            float v1 = acc[mt][nt][1] + b1v;
            float v2 = acc[mt][nt][2] + b0v;
            float v3 = acc[mt][nt][3] + b1v;
            if (EPI == 0) {
                float* base = Cf + obase;
                *(float2*)(base + ra * ldc + cl) = make_float2(v0, v1);
                *(float2*)(base + rb * ldc + cl) = make_float2(v2, v3);
            } else {
                bf16 h0 = __float2bfloat16(v0), h1 = __float2bfloat16(v1);
                bf16 h2 = __float2bfloat16(v2), h3 = __float2bfloat16(v3);
                bf16 l0 = __float2bfloat16(v0 - __bfloat162float(h0));
                bf16 l1 = __float2bfloat16(v1 - __bfloat162float(h1));
                bf16 l2 = __float2bfloat16(v2 - __bfloat162float(h2));
                bf16 l3 = __float2bfloat16(v3 - __bfloat162float(h3));
                bf16* hb = Chi + obase;
                bf16* lb = Clo + obase;
                *(u32*)(hb + ra * ldc + cl) = (u32)__bfloat16_as_ushort(h0) | ((u32)__bfloat16_as_ushort(h1) << 16);
                *(u32*)(hb + rb * ldc + cl) = (u32)__bfloat16_as_ushort(h2) | ((u32)__bfloat16_as_ushort(h3) << 16);
                *(u32*)(lb + ra * ldc + cl) = (u32)__bfloat16_as_ushort(l0) | ((u32)__bfloat16_as_ushort(l1) << 16);
                *(u32*)(lb + rb * ldc + cl) = (u32)__bfloat16_as_ushort(l2) | ((u32)__bfloat16_as_ushort(l3) << 16);
            }
        }
    }
}

// ---------------- fp32 -> bf16 hi/lo split ----------------
__global__ void split_kernel(const float* __restrict__ src, bf16* __restrict__ hi,
                             bf16* __restrict__ lo, int n)
{
    int i = blockIdx.x * 256 + threadIdx.x;
    if (i < n) {
        float v = src[i];
        bf16 h = __float2bfloat16(v);
        hi[i] = h;
        lo[i] = __float2bfloat16(v - __bfloat162float(h));
    }
}

// ---------------- zero fill ----------------
__global__ void zero_kernel(float4* __restrict__ p, long long n4)
{
    long long i = (long long)blockIdx.x * 256 + threadIdx.x;
    const long long stride = (long long)gridDim.x * 256;
    for (; i < n4; i += stride) p[i] = make_float4(0.f, 0.f, 0.f, 0.f);
}

// ---------------- transpose x (b,512,N) -> xT hi/lo (b,N,512) ----------------
__global__ void xpose_kernel(const float* __restrict__ x, bf16* __restrict__ xhi,
                             bf16* __restrict__ xlo)
{
    __shared__ float t[32][33];
    const int b = blockIdx.z;
    const int n0 = blockIdx.x * 32;
    const int c0 = blockIdx.y * 32;
    const int tx = threadIdx.x, ty = threadIdx.y;
    const float* xb = x + (long long)b * CCH * NN;
#pragma unroll
    for (int k = 0; k < 4; k++)
        t[ty + k * 8][tx] = xb[(long long)(c0 + ty + k * 8) * NN + n0 + tx];
    __syncthreads();
    bf16* hb = xhi + (long long)b * NN * CCH;
    bf16* lb = xlo + (long long)b * NN * CCH;
#pragma unroll
    for (int k = 0; k < 4; k++) {
        float v = t[tx][ty + k * 8];
        long long o = (long long)(n0 + ty + k * 8) * CCH + c0 + tx;
        bf16 h = __float2bfloat16(v);
        hb[o] = h;
        lb[o] = __float2bfloat16(v - __bfloat162float(h));
    }
}

// ---------------- 2x2x2 maxpool (from bf16 hi/lo conv planes) + split ----------------
__global__ void pool_kernel(const bf16* __restrict__ gH, const bf16* __restrict__ gL,
                            const bf16* __restrict__ pH, const bf16* __restrict__ pL,
                            bf16* __restrict__ gThi, bf16* __restrict__ gTlo,
                            bf16* __restrict__ phphi, bf16* __restrict__ phplo)
{
    const int m = blockIdx.x;      // 0..1567
    const int b = blockIdx.y;
    const int ci = threadIdx.x;    // 0..255
    const int tp = m / 196;
    const int r = m % 196;
    const int hp = r / 14;
    const int wp = r % 14;
    const long long bb = (long long)b * NN;
    float gm = -1e30f, pm = -1e30f;
#pragma unroll
    for (int dt = 0; dt < 2; dt++)
#pragma unroll
        for (int dh = 0; dh < 2; dh++)
#pragma unroll
            for (int dw = 0; dw < 2; dw++) {
                const long long n = (long long)(2 * tp + dt) * 784 + (2 * hp + dh) * 28 + (2 * wp + dw);
                const long long o = (bb + n) * CIn + ci;
                float gv = __bfloat162float(gH[o]) + __bfloat162float(gL[o]);
                float pv = __bfloat162float(pH[o]) + __bfloat162float(pL[o]);
                gm = fmaxf(gm, gv);
                pm = fmaxf(pm, pv);
            }
    {
        long long o = ((long long)b * MP_F + m) * CIn + ci;
        bf16 h = __float2bfloat16(pm);
        phphi[o] = h;
        phplo[o] = __float2bfloat16(pm - __bfloat162float(h));
    }
    {
        long long o = ((long long)b * CIn + ci) * MP_Y + m;
        bf16 h = __float2bfloat16(gm);
        gThi[o] = h;
        gTlo[o] = __float2bfloat16(gm - __bfloat162float(h));
    }
}

// ---------------- softmax: single global read via smem row cache ----------------
__global__ __launch_bounds__(256)
void softmax_kernel(const float* __restrict__ f, bf16* __restrict__ phi_,
                    bf16* __restrict__ plo_)
{
    __shared__ float row[MMr];
    __shared__ float red[8];
    const long long r = blockIdx.x;
    const float* p = f + r * MP_F;
    bf16* oh = phi_ + r * MP_Y;
    bf16* ol = plo_ + r * MP_Y;
    const int tid = threadIdx.x;
    const int wid = tid >> 5, lane = tid & 31;

    float mx = -1e30f;
    for (int i = tid; i < MMr; i += 256) {
        float v = p[i];
        row[i] = v;
        mx = fmaxf(mx, v);
    }
#pragma unroll
    for (int s = 16; s > 0; s >>= 1) mx = fmaxf(mx, __shfl_xor_sync(~0u, mx, s));
    if (lane == 0) red[wid] = mx;
    __syncthreads();
    {
        float t = red[lane & 7];
#pragma unroll
        for (int s = 4; s > 0; s >>= 1) t = fmaxf(t, __shfl_xor_sync(~0u, t, s));
        mx = t;
    }

    float sum = 0.f;
    for (int i = tid; i < MMr; i += 256) {
        float e = __expf(row[i] - mx);
        row[i] = e;
        sum += e;
    }
#pragma unroll
    for (int s = 16; s > 0; s >>= 1) sum += __shfl_xor_sync(~0u, sum, s);
    __syncthreads();
    if (lane == 0) red[wid] = sum;
    __syncthreads();
    {
        float t = red[lane & 7];
#pragma unroll
        for (int s = 4; s > 0; s >>= 1) t += __shfl_xor_sync(~0u, t, s);
        sum = t;
    }
    const float inv = 1.f / sum;

    for (int i = tid; i < MMr; i += 256) {
        float v = row[i] * inv;
        bf16 h = __float2bfloat16(v);
        oh[i] = h;
        ol[i] = __float2bfloat16(v - __bfloat162float(h));
    }
    if (tid < MP_Y - MMr) {
        oh[MMr + tid] = __ushort_as_bfloat16(0);
        ol[MMr + tid] = __ushort_as_bfloat16(0);
    }
}

// ---------------- BN stats: partial sums then finalize ----------------
__global__ void stats_part(const float* __restrict__ wy, float* __restrict__ part)
{
    const int c = blockIdx.x * 128 + threadIdx.x;
    const int rb = blockIdx.y;                      // 98 row blocks of 512 rows
    const float* p = wy + (long long)rb * 512 * CCH + c;
    float s = 0.f, ss = 0.f;
    for (int r = 0; r < 512; r++) {
        float v = p[(long long)r * CCH];
        s += v;
        ss += v * v;
    }
    part[(long long)rb * 1024 + c] = s;
    part[(long long)rb * 1024 + 512 + c] = ss;
}

__global__ void stats_fin(const float* __restrict__ part, float* __restrict__ stats)
{
    const int c = threadIdx.x;   // 512
    float s = 0.f, ss = 0.f;
    for (int r = 0; r < 98; r++) {
        s += part[r * 1024 + c];
        ss += part[r * 1024 + 512 + c];
    }
    const float cnt = (float)BB * (float)NN;
    const float mean = s / cnt;
    const float var = ss / cnt - mean * mean;
    stats[c] = mean;
    stats[CCH + c] = rsqrtf(var + EPS);
}

// ---------------- final: transpose wy (b,n,c)->(b,c,n), BN affine + residual ----------------
__global__ void final_kernel(const float* __restrict__ wy, const float* __restrict__ x,
                             const float* __restrict__ gamma, const float* __restrict__ beta,
                             const float* __restrict__ stats, float* __restrict__ out)
{
    __shared__ float t[32][33];
    const int b = blockIdx.z;
    const int n0 = blockIdx.x * 32;
    const int c0 = blockIdx.y * 32;
    const int tx = threadIdx.x, ty = threadIdx.y;
    const float* wb = wy + (long long)b * NN * CCH;
#pragma unroll
    for (int k = 0; k < 4; k++)
        t[ty + k * 8][tx] = wb[(long long)(n0 + ty + k * 8) * CCH + c0 + tx];
    __syncthreads();
#pragma unroll
    for (int k = 0; k < 4; k++) {
        const int c = c0 + ty + k * 8;
        const float mean = stats[c];
        const float rstd = stats[CCH + c];
        const float gs = gamma[c] * rstd;
        const float off = beta[c] - mean * gs;
        const long long o = ((long long)b * CCH + c) * NN + n0 + tx;
        out[o] = t[tx][ty + k * 8] * gs + off + x[o];
    }
}

// ---------------- launch ----------------
extern "C" void kernel_launch(void* const* d_in, const int* in_sizes, int n_in,
                              void* d_out, int out_size)
{
    const float* x       = (const float*)d_in[0];
    const float* g_w     = (const float*)d_in[1];
    const float* g_b     = (const float*)d_in[2];
    const float* theta_w = (const float*)d_in[3];
    const float* theta_b = (const float*)d_in[4];
    const float* phi_w   = (const float*)d_in[5];
    const float* phi_b   = (const float*)d_in[6];
    const float* W_w     = (const float*)d_in[7];
    // d_in[8] = W_b: constant channel bias cancels exactly in training-mode BN — skipped.
    const float* gamma   = (const float*)d_in[9];
    const float* beta    = (const float*)d_in[10];
    float* out = (float*)d_out;

    unsigned char* S = nullptr;
    float* stats = nullptr;
    cudaGetSymbolAddress((void**)&S, d_scratch);
    cudaGetSymbolAddress((void**)&stats, d_stats);

    bf16* xt_hi  = (bf16*)(S + XT_HI);
    bf16* xt_lo  = (bf16*)(S + XT_LO);
    float* f     = (float*)(S + F_OFF);
    bf16* conv_hi = (bf16*)(S + CONV_HI);   // [theta | g | phi] planes, each (b,n,256)
    bf16* conv_lo = (bf16*)(S + CONV_LO);
    bf16* th_hi  = conv_hi;                 // seg 0
    bf16* th_lo  = conv_lo;
    bf16* gc_hi  = (bf16*)(S + CONV_HI + CONV_PLANE);       // seg 1
    bf16* gc_lo  = (bf16*)(S + CONV_LO + CONV_PLANE);
    bf16* pc_hi  = (bf16*)(S + CONV_HI + 2 * CONV_PLANE);   // seg 2
    bf16* pc_lo  = (bf16*)(S + CONV_LO + 2 * CONV_PLANE);
    bf16* p_hi   = (bf16*)(S + P_HI);
    bf16* p_lo   = (bf16*)(S + P_LO);
    bf16* y_hi   = (bf16*)(S + Y_HI);
    bf16* y_lo   = (bf16*)(S + Y_LO);
    float* wy    = (float*)(S + WY_OFF);
    bf16* gt_hi  = (bf16*)(S + GT_HI);
    bf16* gt_lo  = (bf16*)(S + GT_LO);
    bf16* php_hi = (bf16*)(S + PHP_HI);
    bf16* php_lo = (bf16*)(S + PHP_LO);
    bf16* wcat_hi = (bf16*)(S + W8_OFF);                    // 768 x 512
    bf16* wcat_lo = (bf16*)(S + W8_OFF + 786432);
    bf16* ww_hi  = (bf16*)(S + W8_OFF + 1572864);           // 512 x 256
    bf16* ww_lo  = (bf16*)(S + W8_OFF + 1835008);
    float* bcat  = (float*)(S + BCAT_OFF);                  // 768
    float* part  = (float*)(S + PART_OFF);

    const int smem = 3 * 32768;   // 96 KB: 3-stage ring
    cudaFuncSetAttribute(tgemm<0, 0>, cudaFuncAttributeMaxDynamicSharedMemorySize, smem);
    cudaFuncSetAttribute(tgemm<1, 0>, cudaFuncAttributeMaxDynamicSharedMemorySize, smem);
    cudaFuncSetAttribute(tgemm<1, 1>, cudaFuncAttributeMaxDynamicSharedMemorySize, smem);

    // concat weight splits: [theta; g; phi] -> wcat (768 x 512)
    split_kernel<<<512, 256>>>(theta_w, wcat_hi, wcat_lo, 131072);
    split_kernel<<<512, 256>>>(g_w, wcat_hi + 131072, wcat_lo + 131072, 131072);
    split_kernel<<<512, 256>>>(phi_w, wcat_hi + 262144, wcat_lo + 262144, 131072);
    split_kernel<<<512, 256>>>(W_w, ww_hi, ww_lo, 131072);

    // concat biases
    cudaMemcpyAsync(bcat, theta_b, 256 * 4, cudaMemcpyDeviceToDevice);
    cudaMemcpyAsync(bcat + 256, g_b, 256 * 4, cudaMemcpyDeviceToDevice);
    cudaMemcpyAsync(bcat + 512, phi_b, 256 * 4, cudaMemcpyDeviceToDevice);

    // zero gt/php pad region (13,369,344 B contiguous at GT_HI)
    zero_kernel<<<2048, 256>>>((float4*)(S + GT_HI), 13369344 / 16);

    // transpose + split x -> xT (b, n, 512)
    xpose_kernel<<<dim3(NN / 32, CCH / 32, BB), dim3(32, 8)>>>(x, xt_hi, xt_lo);

    const long long sXT = (long long)NN * CCH;
    const long long sCI = (long long)NN * CIn;

    // fused conv: [theta|g|phi] = xT @ wcat^T -> bf16 hi/lo planes, seg-routed
    tgemm<1, 1><<<dim3(98, 6, BB), 256, smem>>>(xt_hi, xt_lo, wcat_hi, wcat_lo,
        nullptr, conv_hi, conv_lo, bcat, CCH, CIn, sXT, 0LL, sCI, 4LL * sCI);

    // pool + split: gT (b,256,1600), php (b,1664,256)
    pool_kernel<<<dim3(MMr, BB), 256>>>(gc_hi, gc_lo, pc_hi, pc_lo,
                                        gt_hi, gt_lo, php_hi, php_lo);

    // f = theta @ phi^T : (b, n, 1664) fp32
    tgemm<0, 0><<<dim3(98, MP_F / 128, BB), 256, smem>>>(th_hi, th_lo, php_hi, php_lo,
        f, nullptr, nullptr, nullptr, CIn, MP_F, sCI, (long long)MP_F * CIn,
        (long long)NN * MP_F, 0LL);

    // softmax -> p hi/lo (b, n, 1600)
    softmax_kernel<<<BB * NN, 256>>>(f, p_hi, p_lo);

    // y = p @ gT^T : (b, n, 256) bf16 planes
    tgemm<1, 0><<<dim3(98, 2, BB), 256, smem>>>(p_hi, p_lo, gt_hi, gt_lo,
        nullptr, y_hi, y_lo, nullptr, MP_Y, CIn, (long long)NN * MP_Y,
        (long long)CIn * MP_Y, sCI, 0LL);

    // wy = y @ W_w^T : (b, n, 512) fp32  (W_b dropped: cancels in BN)
    tgemm<0, 0><<<dim3(98, 4, BB), 256, smem>>>(y_hi, y_lo, ww_hi, ww_lo,
        wy, nullptr, nullptr, nullptr, CIn, CCH, sCI, 0LL, (long long)NN * CCH, 0LL);

    // BN stats
    stats_part<<<dim3(4, 98), 128>>>(wy, part);
    stats_fin<<<1, 512>>>(part, stats);

    // transpose + BN affine + residual
    final_kernel<<<dim3(NN / 32, CCH / 32, BB), dim3(32, 8)>>>(wy, x, gamma, beta, stats, out);
}